// round 3
// baseline (speedup 1.0000x reference)
#include <cuda_runtime.h>
#include <math.h>

// ---------------- problem constants ----------------
#define T_STEPS 30
#define BATCH   32
#define HID     512
#define S_LEN   50
#define VOCAB   32000
#define GDIM    1536   // 3*H
#define XK      576    // 512 emb + 64 latent

// ---------------- scratch (device globals; no allocation) ----------------
__device__ float g_kc[S_LEN * BATCH * HID];
__device__ float g_kf[S_LEN * BATCH * HID];
__device__ float g_Pc[S_LEN * BATCH * GDIM];
__device__ float g_Pf[S_LEN * BATCH * GDIM];
__device__ float g_X[T_STEPS * BATCH * XK];
__device__ float g_Wg[GDIM * XK];
__device__ float g_gipre[T_STEPS * BATCH * GDIM];
__device__ float g_q[BATCH * 1024];          // [b][ qc(512) | qf(512) ]
__device__ float g_gh[BATCH * GDIM];
__device__ float g_score[2 * S_LEN * BATCH];
__device__ float g_h[BATCH * HID];
__device__ float g_reluh[T_STEPS * BATCH * HID];

// ---------------- math helpers ----------------
__device__ __forceinline__ float tanhx(float x) {
    float e = __expf(2.0f * x);
    return 1.0f - __fdividef(2.0f, e + 1.0f);
}
__device__ __forceinline__ float sigx(float x) {
    return __fdividef(1.0f, 1.0f + __expf(-x));
}

// ---------------- generic fp32 SGEMM:  C[M,N] = A[M,K] * B[N,K]^T (+bias) ----------------
// Tile 64(M) x 128(N), BK=8, 128 threads, 8x8 micro-tile, double-buffered smem.
// REQUIRES: M%64==0, N%128==0, K%8==0 (true for every call here).
// outmode 0: C[m*N + n]   outmode 1: (m = t*32+b) -> C[(b*30+t)*VOCAB + n]
#define BM 64
#define BN 128
#define BKK 8
__global__ void __launch_bounds__(128) sgemm_nt(
    const float* __restrict__ A, int lda,
    const float* __restrict__ B, int ldb,
    const float* __restrict__ bias,
    float* __restrict__ C,
    int N, int K, int outmode)
{
    __shared__ __align__(16) float As[2][BKK][68];
    __shared__ __align__(16) float Bs[2][BKK][132];

    const int m0 = blockIdx.y * BM;
    const int n0 = blockIdx.x * BN;
    const int tid = threadIdx.x;
    const int tx = tid & 15;          // 0..15
    const int ty = tid >> 4;          // 0..7
    const int tm = ty * 8;
    const int tn = tx * 8;

    const int arow = tid >> 1;            // 0..63
    const int akq  = (tid & 1) * 4;       // 0 or 4
    const int brow = tid;                 // 0..127

    const float* Aptr = A + (size_t)(m0 + arow) * lda + akq;
    const float* Bptr = B + (size_t)(n0 + brow) * ldb;

    float acc[8][8];
    #pragma unroll
    for (int i = 0; i < 8; i++)
        #pragma unroll
        for (int j = 0; j < 8; j++) acc[i][j] = 0.f;

    // preload tile 0
    {
        float4 av  = *(const float4*)(Aptr);
        float4 bv0 = *(const float4*)(Bptr);
        float4 bv1 = *(const float4*)(Bptr + 4);
        As[0][akq + 0][arow] = av.x;  As[0][akq + 1][arow] = av.y;
        As[0][akq + 2][arow] = av.z;  As[0][akq + 3][arow] = av.w;
        Bs[0][0][brow] = bv0.x; Bs[0][1][brow] = bv0.y;
        Bs[0][2][brow] = bv0.z; Bs[0][3][brow] = bv0.w;
        Bs[0][4][brow] = bv1.x; Bs[0][5][brow] = bv1.y;
        Bs[0][6][brow] = bv1.z; Bs[0][7][brow] = bv1.w;
    }
    __syncthreads();

    const int nk = K / BKK;
    for (int kt = 0; kt < nk; kt++) {
        const int cur = kt & 1;
        const int nxt = cur ^ 1;
        float4 pav, pbv0, pbv1;
        const bool more = (kt + 1 < nk);
        if (more) {
            pav  = *(const float4*)(Aptr + (kt + 1) * BKK);
            pbv0 = *(const float4*)(Bptr + (kt + 1) * BKK);
            pbv1 = *(const float4*)(Bptr + (kt + 1) * BKK + 4);
        }
        #pragma unroll
        for (int k = 0; k < BKK; k++) {
            float4 a0 = *(const float4*)&As[cur][k][tm];
            float4 a1 = *(const float4*)&As[cur][k][tm + 4];
            float4 b0 = *(const float4*)&Bs[cur][k][tn];
            float4 b1 = *(const float4*)&Bs[cur][k][tn + 4];
            float ar[8] = {a0.x, a0.y, a0.z, a0.w, a1.x, a1.y, a1.z, a1.w};
            float br[8] = {b0.x, b0.y, b0.z, b0.w, b1.x, b1.y, b1.z, b1.w};
            #pragma unroll
            for (int i = 0; i < 8; i++)
                #pragma unroll
                for (int j = 0; j < 8; j++)
                    acc[i][j] = fmaf(ar[i], br[j], acc[i][j]);
        }
        if (more) {
            As[nxt][akq + 0][arow] = pav.x; As[nxt][akq + 1][arow] = pav.y;
            As[nxt][akq + 2][arow] = pav.z; As[nxt][akq + 3][arow] = pav.w;
            Bs[nxt][0][brow] = pbv0.x; Bs[nxt][1][brow] = pbv0.y;
            Bs[nxt][2][brow] = pbv0.z; Bs[nxt][3][brow] = pbv0.w;
            Bs[nxt][4][brow] = pbv1.x; Bs[nxt][5][brow] = pbv1.y;
            Bs[nxt][6][brow] = pbv1.z; Bs[nxt][7][brow] = pbv1.w;
        }
        __syncthreads();
    }

    // epilogue
    #pragma unroll
    for (int i = 0; i < 8; i++) {
        const int m = m0 + tm + i;
        float* crow;
        if (outmode == 0) {
            crow = C + (size_t)m * N + n0 + tn;
        } else {
            const int t = m >> 5;
            const int b = m & 31;
            crow = C + (size_t)(b * T_STEPS + t) * VOCAB + n0 + tn;
        }
        float4 o0, o1;
        float bb[8];
        #pragma unroll
        for (int j = 0; j < 8; j++)
            bb[j] = bias ? bias[n0 + tn + j] : 0.f;
        o0.x = acc[i][0] + bb[0]; o0.y = acc[i][1] + bb[1];
        o0.z = acc[i][2] + bb[2]; o0.w = acc[i][3] + bb[3];
        o1.x = acc[i][4] + bb[4]; o1.y = acc[i][5] + bb[5];
        o1.z = acc[i][6] + bb[6]; o1.w = acc[i][7] + bb[7];
        *(float4*)(crow)     = o0;
        *(float4*)(crow + 4) = o1;
    }
}

// ---------------- gather kernels ----------------
// X[m=t*32+b][0:512]=emb[token]; [512:576]=latent[b].  token = (t==0)?1:target[t-1][b]
__global__ void gather_X(const int* __restrict__ target,
                         const float* __restrict__ emb,
                         const float* __restrict__ latent)
{
    const int m = blockIdx.x;
    const int t = m >> 5, b = m & 31;
    const int tok = (t == 0) ? 1 : target[(t - 1) * BATCH + b];
    float* xr = g_X + (size_t)m * XK;
    const float* er = emb + (size_t)tok * 512;
    for (int c = threadIdx.x; c < XK; c += blockDim.x)
        xr[c] = (c < 512) ? er[c] : latent[b * 64 + (c - 512)];
}

// Wg[n][0:512]=W_ih[n][0:512]; [512:576]=W_ih[n][1536:1600]
__global__ void gather_Wg(const float* __restrict__ Wih)
{
    const int n = blockIdx.x;
    float* wr = g_Wg + (size_t)n * XK;
    const float* src = Wih + (size_t)n * 1600;
    for (int c = threadIdx.x; c < XK; c += blockDim.x)
        wr[c] = (c < 512) ? src[c] : src[1536 + (c - 512)];
}

__global__ void copy_h(const float* __restrict__ src)
{
    const int i = blockIdx.x * blockDim.x + threadIdx.x;
    if (i < BATCH * HID) g_h[i] = src[i];
}

// ---------------- decode step A: q_c, q_f, gh  (h @ stacked W^T + biases) ----------------
// grid (40, 32) x 256 threads. Block (chunk, b): rows chunk*64 .. +64 of the 2560 stacked outputs.
__global__ void step_qgh(const float* __restrict__ cWh, const float* __restrict__ cbh,
                         const float* __restrict__ fWh, const float* __restrict__ fbh,
                         const float* __restrict__ Whh, const float* __restrict__ bhh)
{
    __shared__ __align__(16) float sh[HID];
    const int b  = blockIdx.y;
    const int g0 = blockIdx.x * 64;
    const int tid = threadIdx.x;
    const int w = tid >> 5, l = tid & 31;

    sh[tid]       = g_h[b * HID + tid];
    sh[tid + 256] = g_h[b * HID + tid + 256];
    __syncthreads();

    #pragma unroll
    for (int i = 0; i < 8; i++) {
        const int r = g0 + w * 8 + i;
        const float* Wrow;
        float bias;
        float* outp;
        if (r < 512)       { Wrow = cWh + (size_t)r * 512;          bias = cbh[r];        outp = g_q + b * 1024 + r; }
        else if (r < 1024) { Wrow = fWh + (size_t)(r - 512) * 512;  bias = fbh[r - 512];  outp = g_q + b * 1024 + r; }
        else               { Wrow = Whh + (size_t)(r - 1024) * 512; bias = bhh[r - 1024]; outp = g_gh + b * GDIM + (r - 1024); }
        float s = 0.f;
        #pragma unroll
        for (int j = 0; j < 4; j++) {
            float4 wv = *(const float4*)(Wrow + j * 128 + l * 4);
            float4 hv = *(const float4*)(sh + j * 128 + l * 4);
            s = fmaf(wv.x, hv.x, s); s = fmaf(wv.y, hv.y, s);
            s = fmaf(wv.z, hv.z, s); s = fmaf(wv.w, hv.w, s);
        }
        #pragma unroll
        for (int o = 16; o; o >>= 1) s += __shfl_xor_sync(0xffffffffu, s, o);
        if (l == 0) *outp = s + bias;
    }
}

// ---------------- decode step B: additive-attention scores ----------------
// grid (50, 2) x 256.  Block (s, a): score[a][s][b] = Wo . tanh(q[a][b]+k[a][s][b]) + bo (masked)
__global__ void step_score(const float* __restrict__ cWo, const float* __restrict__ cbo,
                           const float* __restrict__ fWo, const float* __restrict__ fbo,
                           const int* __restrict__ cmask, const int* __restrict__ fmask)
{
    const int s = blockIdx.x;
    const int a = blockIdx.y;
    const float* kbase = (a ? g_kf : g_kc) + (size_t)(s * BATCH) * HID;
    const float* Wo = a ? fWo : cWo;
    const float  bo = a ? fbo[0] : cbo[0];
    const int* msk = a ? fmask : cmask;

    const int tid = threadIdx.x;
    const int w = tid >> 5, l = tid & 31;

    #pragma unroll
    for (int bi = 0; bi < 4; bi++) {
        const int b = w * 4 + bi;
        const float* kr = kbase + b * HID;
        const float* qr = g_q + b * 1024 + a * 512;
        float sacc = 0.f;
        #pragma unroll
        for (int j = 0; j < 4; j++) {
            float4 kv = *(const float4*)(kr + j * 128 + l * 4);
            float4 qv = *(const float4*)(qr + j * 128 + l * 4);
            float4 wv = *(const float4*)(Wo + j * 128 + l * 4);
            sacc = fmaf(wv.x, tanhx(qv.x + kv.x), sacc);
            sacc = fmaf(wv.y, tanhx(qv.y + kv.y), sacc);
            sacc = fmaf(wv.z, tanhx(qv.z + kv.z), sacc);
            sacc = fmaf(wv.w, tanhx(qv.w + kv.w), sacc);
        }
        #pragma unroll
        for (int o = 16; o; o >>= 1) sacc += __shfl_xor_sync(0xffffffffu, sacc, o);
        if (l == 0) {
            float v = sacc + bo;
            if (msk[s * BATCH + b] == 0) v = -INFINITY;
            g_score[(a * S_LEN + s) * BATCH + b] = v;
        }
    }
}

// ---------------- decode step C: softmax + ctx-gi via P + GRU gates ----------------
// grid (4, 32) x 128.  Block (quarter, b): h-dims [q*128, q*128+128)
__global__ void step_gate(int tstep)
{
    __shared__ float attn[2][S_LEN];
    const int qd = blockIdx.x;
    const int b  = blockIdx.y;
    const int tid = threadIdx.x;
    const int w = tid >> 5, l = tid & 31;

    if (w < 2) {
        const int a = w;
        float v0 = g_score[(a * S_LEN + l) * BATCH + b];
        float v1 = (l < S_LEN - 32) ? g_score[(a * S_LEN + 32 + l) * BATCH + b] : -INFINITY;
        float mx = fmaxf(v0, v1);
        #pragma unroll
        for (int o = 16; o; o >>= 1) mx = fmaxf(mx, __shfl_xor_sync(0xffffffffu, mx, o));
        float e0 = __expf(v0 - mx);
        float e1 = (l < S_LEN - 32) ? __expf(v1 - mx) : 0.f;
        float sm = e0 + e1;
        #pragma unroll
        for (int o = 16; o; o >>= 1) sm += __shfl_xor_sync(0xffffffffu, sm, o);
        float inv = __fdividef(1.f, sm);
        attn[a][l] = e0 * inv;
        if (l < S_LEN - 32) attn[a][32 + l] = e1 * inv;
    }
    __syncthreads();

    const int j = qd * 128 + tid;
    float gr = 0.f, gz = 0.f, gn = 0.f;
    const float* Pc = g_Pc + (size_t)b * GDIM;
    const float* Pf = g_Pf + (size_t)b * GDIM;
    #pragma unroll 2
    for (int s = 0; s < S_LEN; s++) {
        const float ac = attn[0][s];
        const float af = attn[1][s];
        const float* pc = Pc + (size_t)s * BATCH * GDIM;
        const float* pf = Pf + (size_t)s * BATCH * GDIM;
        gr = fmaf(ac, pc[j],        gr); gr = fmaf(af, pf[j],        gr);
        gz = fmaf(ac, pc[512 + j],  gz); gz = fmaf(af, pf[512 + j],  gz);
        gn = fmaf(ac, pc[1024 + j], gn); gn = fmaf(af, pf[1024 + j], gn);
    }
    const float* gip = g_gipre + (size_t)(tstep * BATCH + b) * GDIM;
    const float* ghb = g_gh + (size_t)b * GDIM;
    const float gir = gip[j]        + gr;
    const float giz = gip[512 + j]  + gz;
    const float gin = gip[1024 + j] + gn;
    const float r = sigx(gir + ghb[j]);
    const float z = sigx(giz + ghb[512 + j]);
    const float n = tanhx(gin + r * ghb[1024 + j]);
    const float hv = g_h[b * HID + j];
    const float hn = (1.f - z) * n + z * hv;
    g_h[b * HID + j] = hn;
    g_reluh[(size_t)(tstep * BATCH + b) * HID + j] = fmaxf(hn, 0.f);
}

// ---------------- launcher ----------------
extern "C" void kernel_launch(void* const* d_in, const int* in_sizes, int n_in,
                              void* d_out, int out_size)
{
    (void)in_sizes; (void)n_in; (void)out_size;

    const float* c_memory = (const float*)d_in[0];
    const int*   c_mask   = (const int*)  d_in[1];
    const float* f_memory = (const float*)d_in[2];
    const int*   f_mask   = (const int*)  d_in[3];
    const float* hidden   = (const float*)d_in[4];
    /* d_in[5] cf_attn unused */
    const float* latent   = (const float*)d_in[6];
    const int*   target   = (const int*)  d_in[7];
    const float* emb      = (const float*)d_in[8];
    const float* cW_h = (const float*)d_in[9];
    const float* cb_h = (const float*)d_in[10];
    const float* cW_m = (const float*)d_in[11];
    const float* cb_m = (const float*)d_in[12];
    const float* cW_o = (const float*)d_in[13];
    const float* cb_o = (const float*)d_in[14];
    const float* fW_h = (const float*)d_in[15];
    const float* fb_h = (const float*)d_in[16];
    const float* fW_m = (const float*)d_in[17];
    const float* fb_m = (const float*)d_in[18];
    const float* fW_o = (const float*)d_in[19];
    const float* fb_o = (const float*)d_in[20];
    const float* W_ih = (const float*)d_in[21];
    const float* b_ih = (const float*)d_in[22];
    const float* W_hh = (const float*)d_in[23];
    const float* b_hh = (const float*)d_in[24];
    const float* W_pr = (const float*)d_in[25];
    const float* b_pr = (const float*)d_in[26];
    float* out = (float*)d_out;

    float *kc, *kf, *Pc, *Pf, *X, *Wg, *gipre, *reluh;
    cudaGetSymbolAddress((void**)&kc,    g_kc);
    cudaGetSymbolAddress((void**)&kf,    g_kf);
    cudaGetSymbolAddress((void**)&Pc,    g_Pc);
    cudaGetSymbolAddress((void**)&Pf,    g_Pf);
    cudaGetSymbolAddress((void**)&X,     g_X);
    cudaGetSymbolAddress((void**)&Wg,    g_Wg);
    cudaGetSymbolAddress((void**)&gipre, g_gipre);
    cudaGetSymbolAddress((void**)&reluh, g_reluh);

    // ---- step-invariant precompute ----
    gather_X<<<T_STEPS * BATCH, 256>>>(target, emb, latent);
    gather_Wg<<<GDIM, 256>>>(W_ih);
    copy_h<<<32, 512>>>(hidden);

    // keys: [1600,512] = mem[1600,512] @ Wm[512,512]^T + bm
    sgemm_nt<<<dim3(512 / BN, 1600 / BM), 128>>>(c_memory, 512, cW_m, 512, cb_m, kc, 512, 512, 0);
    sgemm_nt<<<dim3(512 / BN, 1600 / BM), 128>>>(f_memory, 512, fW_m, 512, fb_m, kf, 512, 512, 0);
    // P: [1600,1536] = mem @ (W_ih ctx-slice)^T
    sgemm_nt<<<dim3(GDIM / BN, 1600 / BM), 128>>>(c_memory, 512, W_ih + 512,  1600, nullptr, Pc, GDIM, 512, 0);
    sgemm_nt<<<dim3(GDIM / BN, 1600 / BM), 128>>>(f_memory, 512, W_ih + 1024, 1600, nullptr, Pf, GDIM, 512, 0);
    // gi_pre: [960,1536] = X[960,576] @ Wg[1536,576]^T + b_ih
    sgemm_nt<<<dim3(GDIM / BN, (T_STEPS * BATCH) / BM), 128>>>(X, XK, Wg, XK, b_ih, gipre, GDIM, XK, 0);

    // ---- sequential decode (30 steps x 3 launches) ----
    for (int t = 0; t < T_STEPS; t++) {
        step_qgh<<<dim3(40, BATCH), 256>>>(cW_h, cb_h, fW_h, fb_h, W_hh, b_hh);
        step_score<<<dim3(S_LEN, 2), 256>>>(cW_o, cb_o, fW_o, fb_o, c_mask, f_mask);
        step_gate<<<dim3(4, BATCH), 128>>>(t);
    }

    // ---- deferred vocabulary projection: out[b,t,:] = relu_h[t,b] @ W_proj^T + b_proj ----
    sgemm_nt<<<dim3(VOCAB / BN, (T_STEPS * BATCH) / BM), 128>>>(reluh, HID, W_pr, HID, b_pr, out, VOCAB, 512, 1);
}

// round 5
// speedup vs baseline: 1.5364x; 1.5364x over previous
#include <cuda_runtime.h>
#include <cuda_bf16.h>
#include <math.h>
#include <stdint.h>

// ---------------- problem constants ----------------
#define T_STEPS 30
#define BATCH   32
#define HID     512
#define S_LEN   50
#define VOCAB   32000
#define GDIM    1536   // 3*H
#define XK      576    // 512 emb + 64 latent

// ---------------- fp32 scratch ----------------
__device__ float g_kc[S_LEN * BATCH * HID];
__device__ float g_kf[S_LEN * BATCH * HID];
__device__ float g_Pc[S_LEN * BATCH * GDIM];
__device__ float g_Pf[S_LEN * BATCH * GDIM];
__device__ float g_X[T_STEPS * BATCH * XK];
__device__ float g_Wg[GDIM * XK];
__device__ float g_gipre[T_STEPS * BATCH * GDIM];
__device__ float g_q[BATCH * 1024];
__device__ float g_gh[BATCH * GDIM];
__device__ float g_score[2 * S_LEN * BATCH];
__device__ float g_h[BATCH * HID];
__device__ float g_reluh[T_STEPS * BATCH * HID];

// ---------------- bf16 split (hi/lo) row-major operand buffers ----------------
__device__ __nv_bfloat16 g_cmh[1664 * 512],  g_cml[1664 * 512];     // c_memory  (Mpad 1664)
__device__ __nv_bfloat16 g_fmh[1664 * 512],  g_fml[1664 * 512];     // f_memory
__device__ __nv_bfloat16 g_cwmh[512 * 512],  g_cwml[512 * 512];     // cW_m
__device__ __nv_bfloat16 g_fwmh[512 * 512],  g_fwml[512 * 512];     // fW_m
__device__ __nv_bfloat16 g_wcch[1536 * 512], g_wccl[1536 * 512];    // W_ih ctx-c slice
__device__ __nv_bfloat16 g_wcfh[1536 * 512], g_wcfl[1536 * 512];    // W_ih ctx-f slice
__device__ __nv_bfloat16 g_wgh[1536 * 576],  g_wgl[1536 * 576];     // Wg (emb+latent)
__device__ __nv_bfloat16 g_xh[1024 * 576],   g_xl[1024 * 576];      // X  (Mpad 1024)
__device__ __nv_bfloat16 g_rhh[1024 * 512],  g_rhl[1024 * 512];     // relu(h)
__device__ __nv_bfloat16 g_wph[32000 * 512], g_wpl[32000 * 512];    // W_proj

// ---------------- math helpers ----------------
__device__ __forceinline__ float tanhx(float x) {
    float e = __expf(2.0f * x);
    return 1.0f - __fdividef(2.0f, e + 1.0f);
}
__device__ __forceinline__ float sigx(float x) {
    return __fdividef(1.0f, 1.0f + __expf(-x));
}

// ---------------- PTX helpers (all plain sm_100-safe: sm_80-era ops) ----------------
__device__ __forceinline__ uint32_t smem_u32(const void* p) {
    uint32_t a;
    asm("{ .reg .u64 t; cvta.to.shared.u64 t, %1; cvt.u32.u64 %0, t; }" : "=r"(a) : "l"(p));
    return a;
}
#define CP16(dst, src) asm volatile("cp.async.cg.shared.global [%0], [%1], 16;" :: "r"(dst), "l"(src))
#define CP_COMMIT()    asm volatile("cp.async.commit_group;")
#define CP_WAIT1()     asm volatile("cp.async.wait_group 1;")
#define CP_WAIT0()     asm volatile("cp.async.wait_group 0;")

__device__ __forceinline__ void ldsm4(uint32_t* r, uint32_t addr) {
    asm volatile("ldmatrix.sync.aligned.m8n8.x4.shared.b16 {%0,%1,%2,%3}, [%4];"
        : "=r"(r[0]), "=r"(r[1]), "=r"(r[2]), "=r"(r[3]) : "r"(addr));
}
__device__ __forceinline__ void mma_bf16(float* d, const uint32_t* a, const uint32_t* b) {
    asm volatile("mma.sync.aligned.m16n8k16.row.col.f32.bf16.bf16.f32 "
        "{%0,%1,%2,%3}, {%4,%5,%6,%7}, {%8,%9}, {%0,%1,%2,%3};"
        : "+f"(d[0]), "+f"(d[1]), "+f"(d[2]), "+f"(d[3])
        : "r"(a[0]), "r"(a[1]), "r"(a[2]), "r"(a[3]), "r"(b[0]), "r"(b[1]));
}

// ---------------- fp32 -> split bf16 conversion (row-major, zero-padded rows) ----------------
__global__ void conv_split(const float* __restrict__ src, int ld, int colstart,
                           int R, int K, int Rpad,
                           __nv_bfloat16* __restrict__ hi, __nv_bfloat16* __restrict__ lo)
{
    const int gpr = K >> 3;                 // 8-element granules per row
    const long total = (long)Rpad * gpr;
    for (long idx = (long)blockIdx.x * blockDim.x + threadIdx.x; idx < total;
         idx += (long)gridDim.x * blockDim.x) {
        int r = (int)(idx / gpr);
        int g = (int)(idx - (long)r * gpr);
        float v[8];
        if (r < R) {
            const float* p = src + (size_t)r * ld + colstart + g * 8;
            float4 u0 = *(const float4*)p;
            float4 u1 = *(const float4*)(p + 4);
            v[0] = u0.x; v[1] = u0.y; v[2] = u0.z; v[3] = u0.w;
            v[4] = u1.x; v[5] = u1.y; v[6] = u1.z; v[7] = u1.w;
        } else {
            #pragma unroll
            for (int j = 0; j < 8; j++) v[j] = 0.f;
        }
        __align__(16) unsigned short hb[8];
        __align__(16) unsigned short lb[8];
        #pragma unroll
        for (int j = 0; j < 8; j++) {
            __nv_bfloat16 h = __float2bfloat16(v[j]);
            float hf = __bfloat162float(h);
            __nv_bfloat16 l = __float2bfloat16(v[j] - hf);
            hb[j] = reinterpret_cast<unsigned short&>(h);
            lb[j] = reinterpret_cast<unsigned short&>(l);
        }
        size_t o = (size_t)r * K + (size_t)g * 8;
        *(uint4*)(hi + o) = *(const uint4*)hb;
        *(uint4*)(lo + o) = *(const uint4*)lb;
    }
}

// ---------------- HMMA split-bf16 NT GEMM ----------------
// C[M,Ncols](fp32) = A[M,K]*B[N,K]^T (+bias), via Ah*Bh + Al*Bh + Ah*Bl.
// grid = (Mpad/128, N/128), 256 threads (8 warps, warp tile 32m x 64n).
// smem rows padded to 144B (odd 16B-granule stride -> ldmatrix conflict-free).
// outmode 0: C[m*Ncols+n]   outmode 1: m=t*32+b -> C[(b*30+t)*Ncols+n]
#define ROWB  144
#define TILEA (128 * ROWB)          // 18432
#define STG   (2 * TILEA)           // 36864 per stage (A+B)
#define GSMEM (2 * STG)             // 73728 double-buffered

__global__ void __launch_bounds__(256) mma_gemm(
    const __nv_bfloat16* __restrict__ Ah, const __nv_bfloat16* __restrict__ Al,
    const __nv_bfloat16* __restrict__ Bh, const __nv_bfloat16* __restrict__ Bl,
    int K, const float* __restrict__ bias, float* __restrict__ C,
    int Mreal, int Ncols, int outmode)
{
    extern __shared__ __align__(128) char sm[];
    const int tid = threadIdx.x;
    const int m0 = blockIdx.x * 128;
    const int n0 = blockIdx.y * 128;
    const int nch = K >> 6;
    const int niter = 3 * nch;
    const uint32_t base = smem_u32(sm);

    const int lane = tid & 31, w = tid >> 5;
    const int wm = w & 3, wn = w >> 2;

    float acc[2][8][4];
    #pragma unroll
    for (int a = 0; a < 2; a++)
        #pragma unroll
        for (int b = 0; b < 8; b++)
            #pragma unroll
            for (int c = 0; c < 4; c++) acc[a][b][c] = 0.f;

    // per-thread load coords: 4 granules each for A and B
    const int lr[4] = { (tid + 0) >> 3, (tid + 256) >> 3, (tid + 512) >> 3, (tid + 768) >> 3 };
    const int lg = tid & 7;

    // ---- stage loader ----
    auto load_stage = [&](int i, int stage) {
        const int p  = i / nch;
        const int kc = i - p * nch;
        const __nv_bfloat16* Ag = ((p == 1) ? Al : Ah) + (size_t)m0 * K + kc * 64;
        const __nv_bfloat16* Bg = ((p == 2) ? Bl : Bh) + (size_t)n0 * K + kc * 64;
        const uint32_t dA = base + stage * STG;
        const uint32_t dB = dA + TILEA;
        #pragma unroll
        for (int j = 0; j < 4; j++) {
            const int r = lr[j];
            CP16(dA + r * ROWB + lg * 16, Ag + (size_t)r * K + lg * 8);
            CP16(dB + r * ROWB + lg * 16, Bg + (size_t)r * K + lg * 8);
        }
        CP_COMMIT();
    };

    load_stage(0, 0);

    for (int i = 0; i < niter; i++) {
        const int cur = i & 1;
        if (i + 1 < niter) { load_stage(i + 1, cur ^ 1); CP_WAIT1(); }
        else               { CP_WAIT0(); }
        __syncthreads();

        const uint32_t sA = base + cur * STG;
        const uint32_t sB = sA + TILEA;
        const uint32_t aBase = sA + (uint32_t)(wm * 32 + (lane & 15)) * ROWB + (uint32_t)(lane >> 4) * 16;
        const uint32_t bBase = sB + (uint32_t)(wn * 64 + (lane & 7) + ((lane >> 4) << 3)) * ROWB
                                  + (uint32_t)(((lane >> 3) & 1) << 4);

        #pragma unroll
        for (int ks = 0; ks < 4; ks++) {
            uint32_t af[2][4], bfr[4][4];
            ldsm4(af[0], aBase + ks * 32);
            ldsm4(af[1], aBase + 16 * ROWB + ks * 32);
            #pragma unroll
            for (int ni = 0; ni < 4; ni++)
                ldsm4(bfr[ni], bBase + ni * 16 * ROWB + ks * 32);
            #pragma unroll
            for (int mi = 0; mi < 2; mi++)
                #pragma unroll
                for (int ni = 0; ni < 4; ni++) {
                    mma_bf16(acc[mi][2 * ni],     af[mi], &bfr[ni][0]);
                    mma_bf16(acc[mi][2 * ni + 1], af[mi], &bfr[ni][2]);
                }
        }
        __syncthreads();
    }

    // ---- epilogue ----
    const int ncol0 = n0 + wn * 64 + (lane & 3) * 2;
    #pragma unroll
    for (int mi = 0; mi < 2; mi++) {
        const int ml = wm * 32 + mi * 16 + (lane >> 2);
        #pragma unroll
        for (int half = 0; half < 2; half++) {
            const int m = m0 + ml + half * 8;
            if (m >= Mreal) continue;
            size_t orow = outmode ? ((size_t)(m & 31) * T_STEPS + (m >> 5)) : (size_t)m;
            float* cr = C + orow * Ncols + ncol0;
            #pragma unroll
            for (int nj = 0; nj < 8; nj++) {
                const int c = ncol0 + nj * 8;
                float b0 = bias ? bias[c] : 0.f;
                float b1 = bias ? bias[c + 1] : 0.f;
                float2 v;
                v.x = acc[mi][nj][half * 2 + 0] + b0;
                v.y = acc[mi][nj][half * 2 + 1] + b1;
                *(float2*)(cr + nj * 8) = v;
            }
        }
    }
}

// ---------------- gather kernels ----------------
__global__ void gather_X(const int* __restrict__ target,
                         const float* __restrict__ emb,
                         const float* __restrict__ latent)
{
    const int m = blockIdx.x;
    const int t = m >> 5, b = m & 31;
    const int tok = (t == 0) ? 1 : target[(t - 1) * BATCH + b];
    float* xr = g_X + (size_t)m * XK;
    const float* er = emb + (size_t)tok * 512;
    for (int c = threadIdx.x; c < XK; c += blockDim.x)
        xr[c] = (c < 512) ? er[c] : latent[b * 64 + (c - 512)];
}

__global__ void gather_Wg(const float* __restrict__ Wih)
{
    const int n = blockIdx.x;
    float* wr = g_Wg + (size_t)n * XK;
    const float* src = Wih + (size_t)n * 1600;
    for (int c = threadIdx.x; c < XK; c += blockDim.x)
        wr[c] = (c < 512) ? src[c] : src[1536 + (c - 512)];
}

__global__ void copy_h(const float* __restrict__ src)
{
    const int i = blockIdx.x * blockDim.x + threadIdx.x;
    if (i < BATCH * HID) g_h[i] = src[i];
}

// ---------------- decode step A: q_c, q_f, gh ----------------
__global__ void step_qgh(const float* __restrict__ cWh, const float* __restrict__ cbh,
                         const float* __restrict__ fWh, const float* __restrict__ fbh,
                         const float* __restrict__ Whh, const float* __restrict__ bhh)
{
    __shared__ __align__(16) float sh[HID];
    const int b  = blockIdx.y;
    const int g0 = blockIdx.x * 64;
    const int tid = threadIdx.x;
    const int w = tid >> 5, l = tid & 31;

    sh[tid]       = g_h[b * HID + tid];
    sh[tid + 256] = g_h[b * HID + tid + 256];
    __syncthreads();

    #pragma unroll
    for (int i = 0; i < 8; i++) {
        const int r = g0 + w * 8 + i;
        const float* Wrow;
        float bias;
        float* outp;
        if (r < 512)       { Wrow = cWh + (size_t)r * 512;          bias = cbh[r];        outp = g_q + b * 1024 + r; }
        else if (r < 1024) { Wrow = fWh + (size_t)(r - 512) * 512;  bias = fbh[r - 512];  outp = g_q + b * 1024 + r; }
        else               { Wrow = Whh + (size_t)(r - 1024) * 512; bias = bhh[r - 1024]; outp = g_gh + b * GDIM + (r - 1024); }
        float s = 0.f;
        #pragma unroll
        for (int j = 0; j < 4; j++) {
            float4 wv = *(const float4*)(Wrow + j * 128 + l * 4);
            float4 hv = *(const float4*)(sh + j * 128 + l * 4);
            s = fmaf(wv.x, hv.x, s); s = fmaf(wv.y, hv.y, s);
            s = fmaf(wv.z, hv.z, s); s = fmaf(wv.w, hv.w, s);
        }
        #pragma unroll
        for (int o = 16; o; o >>= 1) s += __shfl_xor_sync(0xffffffffu, s, o);
        if (l == 0) *outp = s + bias;
    }
}

// ---------------- decode step B: attention scores ----------------
__global__ void step_score(const float* __restrict__ cWo, const float* __restrict__ cbo,
                           const float* __restrict__ fWo, const float* __restrict__ fbo,
                           const int* __restrict__ cmask, const int* __restrict__ fmask)
{
    const int s = blockIdx.x;
    const int a = blockIdx.y;
    const float* kbase = (a ? g_kf : g_kc) + (size_t)(s * BATCH) * HID;
    const float* Wo = a ? fWo : cWo;
    const float  bo = a ? fbo[0] : cbo[0];
    const int* msk = a ? fmask : cmask;

    const int tid = threadIdx.x;
    const int w = tid >> 5, l = tid & 31;

    #pragma unroll
    for (int bi = 0; bi < 4; bi++) {
        const int b = w * 4 + bi;
        const float* kr = kbase + b * HID;
        const float* qr = g_q + b * 1024 + a * 512;
        float sacc = 0.f;
        #pragma unroll
        for (int j = 0; j < 4; j++) {
            float4 kv = *(const float4*)(kr + j * 128 + l * 4);
            float4 qv = *(const float4*)(qr + j * 128 + l * 4);
            float4 wv = *(const float4*)(Wo + j * 128 + l * 4);
            sacc = fmaf(wv.x, tanhx(qv.x + kv.x), sacc);
            sacc = fmaf(wv.y, tanhx(qv.y + kv.y), sacc);
            sacc = fmaf(wv.z, tanhx(qv.z + kv.z), sacc);
            sacc = fmaf(wv.w, tanhx(qv.w + kv.w), sacc);
        }
        #pragma unroll
        for (int o = 16; o; o >>= 1) sacc += __shfl_xor_sync(0xffffffffu, sacc, o);
        if (l == 0) {
            float v = sacc + bo;
            if (msk[s * BATCH + b] == 0) v = -INFINITY;
            g_score[(a * S_LEN + s) * BATCH + b] = v;
        }
    }
}

// ---------------- decode step C: softmax + ctx-gi via P + GRU gates ----------------
__global__ void step_gate(int tstep)
{
    __shared__ float attn[2][S_LEN];
    const int qd = blockIdx.x;
    const int b  = blockIdx.y;
    const int tid = threadIdx.x;
    const int w = tid >> 5, l = tid & 31;

    if (w < 2) {
        const int a = w;
        float v0 = g_score[(a * S_LEN + l) * BATCH + b];
        float v1 = (l < S_LEN - 32) ? g_score[(a * S_LEN + 32 + l) * BATCH + b] : -INFINITY;
        float mx = fmaxf(v0, v1);
        #pragma unroll
        for (int o = 16; o; o >>= 1) mx = fmaxf(mx, __shfl_xor_sync(0xffffffffu, mx, o));
        float e0 = __expf(v0 - mx);
        float e1 = (l < S_LEN - 32) ? __expf(v1 - mx) : 0.f;
        float sm = e0 + e1;
        #pragma unroll
        for (int o = 16; o; o >>= 1) sm += __shfl_xor_sync(0xffffffffu, sm, o);
        float inv = __fdividef(1.f, sm);
        attn[a][l] = e0 * inv;
        if (l < S_LEN - 32) attn[a][32 + l] = e1 * inv;
    }
    __syncthreads();

    const int j = qd * 128 + tid;
    float gr = 0.f, gz = 0.f, gn = 0.f;
    const float* Pc = g_Pc + (size_t)b * GDIM;
    const float* Pf = g_Pf + (size_t)b * GDIM;
    #pragma unroll 2
    for (int s = 0; s < S_LEN; s++) {
        const float ac = attn[0][s];
        const float af = attn[1][s];
        const float* pc = Pc + (size_t)s * BATCH * GDIM;
        const float* pf = Pf + (size_t)s * BATCH * GDIM;
        gr = fmaf(ac, pc[j],        gr); gr = fmaf(af, pf[j],        gr);
        gz = fmaf(ac, pc[512 + j],  gz); gz = fmaf(af, pf[512 + j],  gz);
        gn = fmaf(ac, pc[1024 + j], gn); gn = fmaf(af, pf[1024 + j], gn);
    }
    const float* gip = g_gipre + (size_t)(tstep * BATCH + b) * GDIM;
    const float* ghb = g_gh + (size_t)b * GDIM;
    const float gir = gip[j]        + gr;
    const float giz = gip[512 + j]  + gz;
    const float gin = gip[1024 + j] + gn;
    const float r = sigx(gir + ghb[j]);
    const float z = sigx(giz + ghb[512 + j]);
    const float n = tanhx(gin + r * ghb[1024 + j]);
    const float hv = g_h[b * HID + j];
    const float hn = (1.f - z) * n + z * hv;
    g_h[b * HID + j] = hn;
    g_reluh[(size_t)(tstep * BATCH + b) * HID + j] = fmaxf(hn, 0.f);
}

// ---------------- launcher ----------------
static inline int conv_blocks(long Rpad, long K) {
    long total = Rpad * (K / 8);
    long blk = (total + 255) / 256;
    return (int)(blk > 8192 ? 8192 : blk);
}

extern "C" void kernel_launch(void* const* d_in, const int* in_sizes, int n_in,
                              void* d_out, int out_size)
{
    (void)in_sizes; (void)n_in; (void)out_size;

    const float* c_memory = (const float*)d_in[0];
    const int*   c_mask   = (const int*)  d_in[1];
    const float* f_memory = (const float*)d_in[2];
    const int*   f_mask   = (const int*)  d_in[3];
    const float* hidden   = (const float*)d_in[4];
    const float* latent   = (const float*)d_in[6];
    const int*   target   = (const int*)  d_in[7];
    const float* emb      = (const float*)d_in[8];
    const float* cW_h = (const float*)d_in[9];
    const float* cb_h = (const float*)d_in[10];
    const float* cW_m = (const float*)d_in[11];
    const float* cb_m = (const float*)d_in[12];
    const float* cW_o = (const float*)d_in[13];
    const float* cb_o = (const float*)d_in[14];
    const float* fW_h = (const float*)d_in[15];
    const float* fb_h = (const float*)d_in[16];
    const float* fW_m = (const float*)d_in[17];
    const float* fb_m = (const float*)d_in[18];
    const float* fW_o = (const float*)d_in[19];
    const float* fb_o = (const float*)d_in[20];
    const float* W_ih = (const float*)d_in[21];
    const float* b_ih = (const float*)d_in[22];
    const float* W_hh = (const float*)d_in[23];
    const float* b_hh = (const float*)d_in[24];
    const float* W_pr = (const float*)d_in[25];
    const float* b_pr = (const float*)d_in[26];
    float* out = (float*)d_out;

    float *kc, *kf, *Pc, *Pf, *X, *Wg, *gipre, *reluh;
    cudaGetSymbolAddress((void**)&kc,    g_kc);
    cudaGetSymbolAddress((void**)&kf,    g_kf);
    cudaGetSymbolAddress((void**)&Pc,    g_Pc);
    cudaGetSymbolAddress((void**)&Pf,    g_Pf);
    cudaGetSymbolAddress((void**)&X,     g_X);
    cudaGetSymbolAddress((void**)&Wg,    g_Wg);
    cudaGetSymbolAddress((void**)&gipre, g_gipre);
    cudaGetSymbolAddress((void**)&reluh, g_reluh);

    __nv_bfloat16 *cmh, *cml, *fmh, *fml, *cwmh, *cwml, *fwmh, *fwml;
    __nv_bfloat16 *wcch, *wccl, *wcfh, *wcfl, *wgh, *wgl, *xh, *xl, *rhh, *rhl, *wph, *wpl;
    cudaGetSymbolAddress((void**)&cmh,  g_cmh);  cudaGetSymbolAddress((void**)&cml,  g_cml);
    cudaGetSymbolAddress((void**)&fmh,  g_fmh);  cudaGetSymbolAddress((void**)&fml,  g_fml);
    cudaGetSymbolAddress((void**)&cwmh, g_cwmh); cudaGetSymbolAddress((void**)&cwml, g_cwml);
    cudaGetSymbolAddress((void**)&fwmh, g_fwmh); cudaGetSymbolAddress((void**)&fwml, g_fwml);
    cudaGetSymbolAddress((void**)&wcch, g_wcch); cudaGetSymbolAddress((void**)&wccl, g_wccl);
    cudaGetSymbolAddress((void**)&wcfh, g_wcfh); cudaGetSymbolAddress((void**)&wcfl, g_wcfl);
    cudaGetSymbolAddress((void**)&wgh,  g_wgh);  cudaGetSymbolAddress((void**)&wgl,  g_wgl);
    cudaGetSymbolAddress((void**)&xh,   g_xh);   cudaGetSymbolAddress((void**)&xl,   g_xl);
    cudaGetSymbolAddress((void**)&rhh,  g_rhh);  cudaGetSymbolAddress((void**)&rhl,  g_rhl);
    cudaGetSymbolAddress((void**)&wph,  g_wph);  cudaGetSymbolAddress((void**)&wpl,  g_wpl);

    cudaFuncSetAttribute(mma_gemm, cudaFuncAttributeMaxDynamicSharedMemorySize, GSMEM);

    // ---- gathers + conversions (step-invariant) ----
    gather_X<<<T_STEPS * BATCH, 256>>>(target, emb, latent);
    gather_Wg<<<GDIM, 256>>>(W_ih);
    copy_h<<<32, 512>>>(hidden);

    conv_split<<<conv_blocks(1664, 512), 256>>>(c_memory, 512, 0, 1600, 512, 1664, cmh, cml);
    conv_split<<<conv_blocks(1664, 512), 256>>>(f_memory, 512, 0, 1600, 512, 1664, fmh, fml);
    conv_split<<<conv_blocks(512, 512), 256>>>(cW_m, 512, 0, 512, 512, 512, cwmh, cwml);
    conv_split<<<conv_blocks(512, 512), 256>>>(fW_m, 512, 0, 512, 512, 512, fwmh, fwml);
    conv_split<<<conv_blocks(1536, 512), 256>>>(W_ih, 1600, 512,  1536, 512, 1536, wcch, wccl);
    conv_split<<<conv_blocks(1536, 512), 256>>>(W_ih, 1600, 1024, 1536, 512, 1536, wcfh, wcfl);
    conv_split<<<conv_blocks(1536, 576), 256>>>(Wg, 576, 0, 1536, 576, 1536, wgh, wgl);
    conv_split<<<conv_blocks(1024, 576), 256>>>(X, 576, 0, 960, 576, 1024, xh, xl);
    conv_split<<<conv_blocks(32000, 512), 256>>>(W_pr, 512, 0, 32000, 512, 32000, wph, wpl);

    // ---- precompute GEMMs (HMMA) ----
    mma_gemm<<<dim3(13, 4),  256, GSMEM>>>(cmh, cml, cwmh, cwml, 512, cb_m, kc, 1600, 512, 0);
    mma_gemm<<<dim3(13, 4),  256, GSMEM>>>(fmh, fml, fwmh, fwml, 512, fb_m, kf, 1600, 512, 0);
    mma_gemm<<<dim3(13, 12), 256, GSMEM>>>(cmh, cml, wcch, wccl, 512, nullptr, Pc, 1600, GDIM, 0);
    mma_gemm<<<dim3(13, 12), 256, GSMEM>>>(fmh, fml, wcfh, wcfl, 512, nullptr, Pf, 1600, GDIM, 0);
    mma_gemm<<<dim3(8, 12),  256, GSMEM>>>(xh, xl, wgh, wgl, 576, b_ih, gipre, 960, GDIM, 0);

    // ---- sequential decode (30 steps x 3 launches) ----
    for (int t = 0; t < T_STEPS; t++) {
        step_qgh<<<dim3(40, BATCH), 256>>>(cW_h, cb_h, fW_h, fb_h, W_hh, b_hh);
        step_score<<<dim3(S_LEN, 2), 256>>>(cW_o, cb_o, fW_o, fb_o, c_mask, f_mask);
        step_gate<<<dim3(4, BATCH), 128>>>(t);
    }

    // ---- deferred vocabulary projection (HMMA) ----
    conv_split<<<conv_blocks(1024, 512), 256>>>(reluh, 512, 0, 960, 512, 1024, rhh, rhl);
    mma_gemm<<<dim3(8, 250), 256, GSMEM>>>(rhh, rhl, wph, wpl, 512, b_pr, out, 960, VOCAB, 1);
}